// round 13
// baseline (speedup 1.0000x reference)
#include <cuda_runtime.h>
#include <cuda_fp16.h>
#include <math.h>
#include <stdint.h>

// Problem constants
#define B_  16
#define T_  4096
#define D_  1024
#define U_  1024
#define M_  (B_ * T_)   // 65536 rows

// ---------------------------------------------------------------------------
// Device-global scratch (no allocations allowed)
// ---------------------------------------------------------------------------
__device__ __half g_Xhi[(size_t)M_ * D_];   // fp16 of enc (published by n0==0 CTAs)
__device__ __half g_Whi[(size_t)U_ * D_];   // W2^T [u][d] fp16
__device__ float g_hpb[B_ * U_];
__device__ float g_score[M_];

// ---------------------------------------------------------------------------
// Helpers
// ---------------------------------------------------------------------------
__device__ __forceinline__ uint32_t smem_u32(const void* p) {
    uint32_t a;
    asm("{ .reg .u64 t; cvta.to.shared.u64 t, %1; cvt.u32.u64 %0, t; }" : "=r"(a) : "l"(p));
    return a;
}
#define CP_ASYNC16(dst, src) \
    asm volatile("cp.async.cg.shared.global [%0], [%1], 16;" :: "r"(dst), "l"(src))
#define CP_COMMIT() asm volatile("cp.async.commit_group;" ::: "memory")
#define CP_WAIT1()  asm volatile("cp.async.wait_group 1;" ::: "memory")

__device__ __forceinline__ void ldm_x4(uint32_t* r, uint32_t addr) {
    asm volatile("ldmatrix.sync.aligned.m8n8.x4.shared.b16 {%0,%1,%2,%3}, [%4];"
                 : "=r"(r[0]), "=r"(r[1]), "=r"(r[2]), "=r"(r[3]) : "r"(addr));
}
__device__ __forceinline__ void mma_fp16(float* c, const uint32_t* a, const uint32_t* b) {
    asm volatile(
        "mma.sync.aligned.m16n8k16.row.col.f32.f16.f16.f32 "
        "{%0,%1,%2,%3}, {%4,%5,%6,%7}, {%8,%9}, {%0,%1,%2,%3};"
        : "+f"(c[0]), "+f"(c[1]), "+f"(c[2]), "+f"(c[3])
        : "r"(a[0]), "r"(a[1]), "r"(a[2]), "r"(a[3]), "r"(b[0]), "r"(b[1]));
}

// FMA-only fast tanh (abs err ~1e-6); avoids MUFU entirely.
__device__ __forceinline__ float fast_tanh(float x) {
    float ax = fabsf(x);
    float t = fminf(ax * 2.885390082f, 30.0f);     // 2|x|*log2(e)
    float nt = -t;
    float fi = floorf(nt);
    float f = nt - fi;                              // [0,1)
    float p =              1.5253232e-5f;
    p = fmaf(p, f, 1.5403530e-4f);
    p = fmaf(p, f, 1.3333558e-3f);
    p = fmaf(p, f, 9.6181291e-3f);
    p = fmaf(p, f, 5.5504109e-2f);
    p = fmaf(p, f, 2.4022651e-1f);
    p = fmaf(p, f, 6.9314718e-1f);
    p = fmaf(p, f, 1.0f);
    int ei = (int)fi;                               // [-30, 0]
    float e = __int_as_float((ei + 127) << 23) * p; // 2^nt = e^{-2|x|}
    float d = 1.0f + e;
    float r = __int_as_float(0x7EF311C3u - __float_as_int(d));
    r = r * (2.0f - d * r);
    r = r * (2.0f - d * r);
    r = r * (2.0f - d * r);
    float y = (1.0f - e) * r;
    return copysignf(y, x);
}

// ---------------------------------------------------------------------------
// Kernel B: transpose W2 [d][u] -> [u][d] fp16
// ---------------------------------------------------------------------------
__global__ void convert_w_kernel(const float* __restrict__ W2) {
    __shared__ float tile[32][33];
    const int u0 = blockIdx.x * 32, d0 = blockIdx.y * 32;
    const int tx = threadIdx.x, ty = threadIdx.y;           // (32, 8)
    #pragma unroll
    for (int j = 0; j < 32; j += 8)
        tile[ty + j][tx] = W2[(size_t)(d0 + ty + j) * U_ + u0 + tx];
    __syncthreads();
    #pragma unroll
    for (int j = 0; j < 32; j += 8)
        g_Whi[(size_t)(u0 + ty + j) * D_ + d0 + tx] =
            __float2half_rn(tile[tx][ty + j]);
}

// ---------------------------------------------------------------------------
// Kernel C: hpb[b,u] = h@W1 + b1 + b2
// ---------------------------------------------------------------------------
__global__ void hproj_kernel(const float* __restrict__ h,
                             const float* __restrict__ W1,
                             const float* __restrict__ b1,
                             const float* __restrict__ b2) {
    __shared__ float hs[D_];
    const int b = blockIdx.y;
    const int u = blockIdx.x * 256 + threadIdx.x;
    for (int i = threadIdx.x; i < D_; i += 256) hs[i] = h[b * D_ + i];
    __syncthreads();
    float acc = 0.f;
    #pragma unroll 8
    for (int d = 0; d < D_; d++) acc = fmaf(hs[d], W1[d * U_ + u], acc);
    g_hpb[b * U_ + u] = acc + b1[u] + b2[u];
}

// ---------------------------------------------------------------------------
// Kernel D: score GEMM (mma.sync fp16) with fp32->fp16 A-conversion hidden
// behind the MMA stream. KEY FIX vs R12: each thread cp.asyncs exactly the
// A32 region it later converts (row tid>>1, half tid&1), so wait_group 1
// makes those bytes visible to the converting thread WITHOUT a barrier.
// A16 double-buffered, A32 x2, B x3, one barrier per chunk.
// 256 threads / 8 warps, 64x64 warp tiles, K chunks of 64.
// ---------------------------------------------------------------------------
#define ROWB      144                     // fp16 row: 128 B data + 16 B pad
#define ROWB32    272                     // fp32 row: 256 B data + 16 B pad
#define A32_TILE  (128 * ROWB32)          // 34816
#define B_TILE    (256 * ROWB)            // 36864
#define A16_TILE  (128 * ROWB)            // 18432
#define OFF_B     (2 * A32_TILE)          // 69632
#define OFF_A16   (OFF_B + 3 * B_TILE)    // 180224
#define OFF_VH    (OFF_A16 + 2 * A16_TILE)// 217088
#define OFF_RED   (OFF_VH + 2048)         // 219136
#define SK_SMEM   (OFF_RED + 2048)        // 221184  (< 227KB cap)

__global__ void __launch_bounds__(256, 1)
score_kernel(const float* __restrict__ X, const float* __restrict__ V) {
    extern __shared__ char smem[];
    const uint32_t sb = smem_u32(smem);
    const int tid = threadIdx.x;
    const int lane = tid & 31;
    const int wid = tid >> 5;
    const int warp_m = wid >> 2;        // 0..1  (64 rows each)
    const int warp_n = wid & 3;         // 0..3  (64 cols each)
    const int row0 = (blockIdx.x >> 2) * 128;   // row block
    const int n0   = (blockIdx.x & 3) * 256;    // u-pass
    const int b = row0 >> 12;

    float* vbuf = (float*)(smem + OFF_VH);
    float* hbuf = (float*)(smem + OFF_VH + 1024);
    float* red  = (float*)(smem + OFF_RED);

    const uint32_t a_loff = (uint32_t)((lane & 15) * ROWB + (lane >> 4) * 16);
    const uint32_t b_loff = (uint32_t)(((lane & 7) + ((lane >> 4) << 3)) * ROWB
                                       + ((lane >> 3) & 1) * 16);

    vbuf[tid] = V[n0 + tid];
    hbuf[tid] = g_hpb[b * U_ + n0 + tid];

    float acc[4][8][4];                // 128 fp32 accumulators
    #pragma unroll
    for (int mt = 0; mt < 4; mt++)
        #pragma unroll
        for (int nt = 0; nt < 8; nt++)
            #pragma unroll
            for (int c = 0; c < 4; c++) acc[mt][nt][c] = 0.f;

    const int cr = tid >> 1;            // this thread's A row (load + convert)
    const int ch = tid & 1;             // this thread's 32-float half

    // ---- loader: chunk j -> A32[j&1] (self-owned region), B[j%3] ----
    auto load_stage = [&](int j) {
        const int k0 = j * 64;
        const uint32_t a32 = sb + (j & 1) * A32_TILE + cr * ROWB32 + ch * 128;
        const float* asrc = X + (size_t)(row0 + cr) * D_ + k0 + ch * 32;
        #pragma unroll
        for (int i = 0; i < 8; i++)            // A fp32: own 32 floats
            CP_ASYNC16(a32 + i * 16, asrc + i * 4);
        const uint32_t bst = sb + OFF_B + (j % 3) * B_TILE;
        #pragma unroll
        for (int it = 0; it < 8; it++) {       // B fp16: 256 rows x 8 chunks
            const int task = tid + it * 256;
            const int r = task >> 3, c = task & 7;
            CP_ASYNC16(bst + r * ROWB + c * 16,
                       g_Whi + (size_t)(n0 + r) * D_ + k0 + c * 8);
        }
    };

    // ---- convert: OWN A32 region -> A16[j&1]; publish g_Xhi if pass 0 ----
    auto convert = [&](int j) {
        const char* src = smem + (j & 1) * A32_TILE + cr * ROWB32 + ch * 128;
        char* dst = smem + OFF_A16 + (j & 1) * A16_TILE + cr * ROWB + ch * 64;
        uint4 st[4];
        #pragma unroll
        for (int i = 0; i < 4; i++) {
            float4 f0 = *(const float4*)(src + i * 32);
            float4 f1 = *(const float4*)(src + i * 32 + 16);
            __half2 h0 = __floats2half2_rn(f0.x, f0.y);
            __half2 h1 = __floats2half2_rn(f0.z, f0.w);
            __half2 h2 = __floats2half2_rn(f1.x, f1.y);
            __half2 h3 = __floats2half2_rn(f1.z, f1.w);
            st[i].x = *(uint32_t*)&h0;  st[i].y = *(uint32_t*)&h1;
            st[i].z = *(uint32_t*)&h2;  st[i].w = *(uint32_t*)&h3;
            *(uint4*)(dst + i * 16) = st[i];
        }
        if (n0 == 0) {
            #pragma unroll
            for (int i = 0; i < 4; i++)
                *(uint4*)(g_Xhi + (size_t)(row0 + cr) * D_
                          + j * 64 + ch * 32 + i * 8) = st[i];
        }
    };

    // ---- prologue ----
    load_stage(0); CP_COMMIT();
    load_stage(1); CP_COMMIT();
    CP_WAIT1();                 // own chunk-0 copies visible
    convert(0);
    __syncthreads();            // A16[0] published to all warps

    #pragma unroll 1
    for (int kc = 0; kc < 16; kc++) {
        // MMA for chunk kc (A16[kc&1] converted last iter; B[kc%3] landed)
        const uint32_t aBase = sb + OFF_A16 + (kc & 1) * A16_TILE
                             + warp_m * 64 * ROWB + a_loff;
        const uint32_t bBase = sb + OFF_B + (kc % 3) * B_TILE
                             + warp_n * 64 * ROWB + b_loff;
        #pragma unroll
        for (int k16 = 0; k16 < 4; k16++) {
            const uint32_t ko = k16 * 32;
            uint32_t af[4][4], bf[4][4];
            #pragma unroll
            for (int i = 0; i < 4; i++)
                ldm_x4(bf[i], bBase + i * 16 * ROWB + ko);
            #pragma unroll
            for (int mt = 0; mt < 4; mt++)
                ldm_x4(af[mt], aBase + mt * 16 * ROWB + ko);
            #pragma unroll
            for (int mt = 0; mt < 4; mt++)
                #pragma unroll
                for (int nt = 0; nt < 8; nt++)
                    mma_fp16(acc[mt][nt], af[mt], &bf[nt >> 1][(nt & 1) * 2]);
        }

        if (kc + 2 < 16) load_stage(kc + 2);
        CP_COMMIT();
        CP_WAIT1();                       // own chunk kc+1 copies visible
        if (kc + 1 < 16) convert(kc + 1); // self-owned data: no barrier needed
        __syncthreads();                  // publish A16 + B visibility for kc+1
    }

    // ---- epilogue: fold tanh + V into per-row partials ----
    float rowsum8[8];
    #pragma unroll
    for (int j = 0; j < 8; j++) rowsum8[j] = 0.f;
    #pragma unroll
    for (int mt = 0; mt < 4; mt++)
        #pragma unroll
        for (int nt = 0; nt < 8; nt++)
            #pragma unroll
            for (int c = 0; c < 4; c++) {
                const int ul = warp_n * 64 + nt * 8 + (lane & 3) * 2 + (c & 1);
                const float s = acc[mt][nt][c] + hbuf[ul];
                rowsum8[mt * 2 + (c >> 1)] =
                    fmaf(vbuf[ul], fast_tanh(s), rowsum8[mt * 2 + (c >> 1)]);
            }

    // cross-thread reduction: quad-shfl, then 4 warp_n slices via smem
    #pragma unroll
    for (int j = 0; j < 8; j++) {
        float v = rowsum8[j];
        v += __shfl_xor_sync(0xffffffffu, v, 1);
        v += __shfl_xor_sync(0xffffffffu, v, 2);
        if ((lane & 3) == 0) {
            const int r = warp_m * 64 + (j >> 1) * 16 + (lane >> 2) + 8 * (j & 1);
            red[r * 4 + warp_n] = v;
        }
    }
    __syncthreads();
    if (tid < 128)
        atomicAdd(&g_score[row0 + tid],
                  red[tid * 4 + 0] + red[tid * 4 + 1]
                + red[tid * 4 + 2] + red[tid * 4 + 3]);
}

// ---------------------------------------------------------------------------
// Kernel E: softmax over T per batch (bv constant -> softmax-invariant)
// ---------------------------------------------------------------------------
__global__ void softmax_kernel(float* __restrict__ wout) {
    const int b = blockIdx.x;
    const float* s = g_score + b * T_;
    float* w = wout + b * T_;
    __shared__ float red[256];
    const int tid = threadIdx.x;

    float mx = -INFINITY;
    for (int t = tid; t < T_; t += 256) mx = fmaxf(mx, s[t]);
    red[tid] = mx; __syncthreads();
    for (int o = 128; o > 0; o >>= 1) {
        if (tid < o) red[tid] = fmaxf(red[tid], red[tid + o]);
        __syncthreads();
    }
    mx = red[0]; __syncthreads();

    float sum = 0.f;
    for (int t = tid; t < T_; t += 256) {
        const float e = expf(s[t] - mx);
        w[t] = e;
        sum += e;
    }
    red[tid] = sum; __syncthreads();
    for (int o = 128; o > 0; o >>= 1) {
        if (tid < o) red[tid] += red[tid + o];
        __syncthreads();
    }
    const float inv = 1.f / red[0];
    for (int t = tid; t < T_; t += 256) w[t] *= inv;
}

// ---------------------------------------------------------------------------
// Kernel F: context[b,d] = sum_t w[b,t] * enc_fp16[b,t,d]
// ---------------------------------------------------------------------------
__global__ void context_kernel(const float* __restrict__ w,
                               float* __restrict__ ctx) {
    const int b  = blockIdx.y;
    const int t0 = blockIdx.x * 128;
    const int tid = threadIdx.x;
    float c[4] = {0.f, 0.f, 0.f, 0.f};
    for (int t = t0; t < t0 + 128; t++) {
        const float wt = w[b * T_ + t];
        const __half* row = g_Xhi + ((size_t)b * T_ + t) * D_;
        #pragma unroll
        for (int j = 0; j < 4; j++)
            c[j] = fmaf(wt, __half2float(row[tid + j * 256]), c[j]);
    }
    #pragma unroll
    for (int j = 0; j < 4; j++)
        atomicAdd(&ctx[b * D_ + tid + j * 256], c[j]);
}

// ---------------------------------------------------------------------------
extern "C" void kernel_launch(void* const* d_in, const int* in_sizes, int n_in,
                              void* d_out, int out_size) {
    const float* h   = (const float*)d_in[0];  // [B, D]
    const float* enc = (const float*)d_in[1];  // [B, T, D]
    const float* W1  = (const float*)d_in[2];  // [D, U]
    const float* b1  = (const float*)d_in[3];  // [U]
    const float* W2  = (const float*)d_in[4];  // [D, U]
    const float* b2  = (const float*)d_in[5];  // [U]
    const float* V   = (const float*)d_in[6];  // [U, 1]
    // d_in[7] = bv: softmax-invariant constant, unused.

    float* out = (float*)d_out;
    float* ctx = out;             // [B, D]
    float* wts = out + B_ * D_;   // [B, T, 1]

    cudaFuncSetAttribute(score_kernel,
                         cudaFuncAttributeMaxDynamicSharedMemorySize, SK_SMEM);

    void* scorePtr = nullptr;
    cudaGetSymbolAddress(&scorePtr, g_score);

    cudaMemsetAsync(ctx, 0, (size_t)B_ * D_ * sizeof(float));
    cudaMemsetAsync(scorePtr, 0, (size_t)M_ * sizeof(float));

    convert_w_kernel<<<dim3(32, 32), dim3(32, 8)>>>(W2);
    hproj_kernel<<<dim3(U_ / 256, B_), 256>>>(h, W1, b1, b2);
    score_kernel<<<4 * (M_ / 128), 256, SK_SMEM>>>(enc, V);
    softmax_kernel<<<B_, 256>>>(wts);
    context_kernel<<<dim3(T_ / 128, B_), 256>>>(wts, ctx);
}

// round 14
// speedup vs baseline: 1.3039x; 1.3039x over previous
#include <cuda_runtime.h>
#include <cuda_fp16.h>
#include <math.h>
#include <stdint.h>

// Problem constants
#define B_  16
#define T_  4096
#define D_  1024
#define U_  1024
#define M_  (B_ * T_)   // 65536 rows

// ---------------------------------------------------------------------------
// Device-global scratch (no allocations allowed)
// ---------------------------------------------------------------------------
__device__ __half g_Xhi[(size_t)M_ * D_];   // 128 MiB  (fp16 of enc)
__device__ __half g_Whi[(size_t)U_ * D_];   // W2^T [u][d] fp16
__device__ float g_hpb[B_ * U_];
__device__ float g_score[M_];

// ---------------------------------------------------------------------------
// Helpers
// ---------------------------------------------------------------------------
__device__ __forceinline__ uint32_t smem_u32(const void* p) {
    uint32_t a;
    asm("{ .reg .u64 t; cvta.to.shared.u64 t, %1; cvt.u32.u64 %0, t; }" : "=r"(a) : "l"(p));
    return a;
}
#define CP_ASYNC16(dst, src) \
    asm volatile("cp.async.cg.shared.global [%0], [%1], 16;" :: "r"(dst), "l"(src))
#define CP_COMMIT() asm volatile("cp.async.commit_group;" ::: "memory")
#define CP_WAIT1()  asm volatile("cp.async.wait_group 1;" ::: "memory")

__device__ __forceinline__ void ldm_x4(uint32_t* r, uint32_t addr) {
    asm volatile("ldmatrix.sync.aligned.m8n8.x4.shared.b16 {%0,%1,%2,%3}, [%4];"
                 : "=r"(r[0]), "=r"(r[1]), "=r"(r[2]), "=r"(r[3]) : "r"(addr));
}
__device__ __forceinline__ void mma_fp16(float* c, const uint32_t* a, const uint32_t* b) {
    asm volatile(
        "mma.sync.aligned.m16n8k16.row.col.f32.f16.f16.f32 "
        "{%0,%1,%2,%3}, {%4,%5,%6,%7}, {%8,%9}, {%0,%1,%2,%3};"
        : "+f"(c[0]), "+f"(c[1]), "+f"(c[2]), "+f"(c[3])
        : "r"(a[0]), "r"(a[1]), "r"(a[2]), "r"(a[3]), "r"(b[0]), "r"(b[1]));
}

// FMA-only fast tanh (abs err ~1e-6); avoids MUFU entirely.
__device__ __forceinline__ float fast_tanh(float x) {
    float ax = fabsf(x);
    float t = fminf(ax * 2.885390082f, 30.0f);     // 2|x|*log2(e)
    float nt = -t;
    float fi = floorf(nt);
    float f = nt - fi;                              // [0,1)
    float p =              1.5253232e-5f;
    p = fmaf(p, f, 1.5403530e-4f);
    p = fmaf(p, f, 1.3333558e-3f);
    p = fmaf(p, f, 9.6181291e-3f);
    p = fmaf(p, f, 5.5504109e-2f);
    p = fmaf(p, f, 2.4022651e-1f);
    p = fmaf(p, f, 6.9314718e-1f);
    p = fmaf(p, f, 1.0f);
    int ei = (int)fi;                               // [-30, 0]
    float e = __int_as_float((ei + 127) << 23) * p; // 2^nt = e^{-2|x|}
    float d = 1.0f + e;
    float r = __int_as_float(0x7EF311C3u - __float_as_int(d));
    r = r * (2.0f - d * r);
    r = r * (2.0f - d * r);
    r = r * (2.0f - d * r);
    float y = (1.0f - e) * r;
    return copysignf(y, x);
}

// ---------------------------------------------------------------------------
// Kernel A: enc fp32 -> fp16
// ---------------------------------------------------------------------------
__global__ void convert_x_kernel(const float* __restrict__ X) {
    size_t i = ((size_t)blockIdx.x * 256 + threadIdx.x) * 8;
    float4 a = *(const float4*)(X + i);
    float4 b = *(const float4*)(X + i + 4);
    float v[8] = {a.x, a.y, a.z, a.w, b.x, b.y, b.z, b.w};
    __half hi[8];
    #pragma unroll
    for (int j = 0; j < 8; j++) hi[j] = __float2half_rn(v[j]);
    *(uint4*)(g_Xhi + i) = *(uint4*)hi;
}

// ---------------------------------------------------------------------------
// Kernel B: transpose W2 [d][u] -> [u][d] fp16
// ---------------------------------------------------------------------------
__global__ void convert_w_kernel(const float* __restrict__ W2) {
    __shared__ float tile[32][33];
    const int u0 = blockIdx.x * 32, d0 = blockIdx.y * 32;
    const int tx = threadIdx.x, ty = threadIdx.y;           // (32, 8)
    #pragma unroll
    for (int j = 0; j < 32; j += 8)
        tile[ty + j][tx] = W2[(size_t)(d0 + ty + j) * U_ + u0 + tx];
    __syncthreads();
    #pragma unroll
    for (int j = 0; j < 32; j += 8)
        g_Whi[(size_t)(u0 + ty + j) * D_ + d0 + tx] =
            __float2half_rn(tile[tx][ty + j]);
}

// ---------------------------------------------------------------------------
// Kernel C: hpb[b,u] = h@W1 + b1 + b2
// ---------------------------------------------------------------------------
__global__ void hproj_kernel(const float* __restrict__ h,
                             const float* __restrict__ W1,
                             const float* __restrict__ b1,
                             const float* __restrict__ b2) {
    __shared__ float hs[D_];
    const int b = blockIdx.y;
    const int u = blockIdx.x * 256 + threadIdx.x;
    for (int i = threadIdx.x; i < D_; i += 256) hs[i] = h[b * D_ + i];
    __syncthreads();
    float acc = 0.f;
    #pragma unroll 8
    for (int d = 0; d < D_; d++) acc = fmaf(hs[d], W1[d * U_ + u], acc);
    g_hpb[b * U_ + u] = acc + b1[u] + b2[u];
}

// ---------------------------------------------------------------------------
// Kernel D: score GEMM via mma.sync fp16 (single product), fused tanh/V
// epilogue. Grid = 2048 (row-block x u-pass), atomicAdd partial row sums.
// K chunks of 64, 3-stage cp.async pipeline, 256 threads / 8 warps,
// 64x64 warp tiles. (R9 structure — at the HMMA issue-rate wall.)
// ---------------------------------------------------------------------------
#define ROWB     144                      // 128 B data + 16 B pad
#define A_TILE   (128 * ROWB)             // 18432
#define B_TILE   (256 * ROWB)             // 36864
#define STAGE_SZ (A_TILE + B_TILE)        // 55296
#define OFF_B    A_TILE
#define NSTAGE   3
#define OFF_VH   (NSTAGE * STAGE_SZ)      // 165888
#define OFF_RED  (OFF_VH + 2048)
#define SK_SMEM  (OFF_RED + 4096)         // 172032

__global__ void __launch_bounds__(256, 1)
score_kernel(const float* __restrict__ V) {
    extern __shared__ char smem[];
    const uint32_t sb = smem_u32(smem);
    const int tid = threadIdx.x;
    const int lane = tid & 31;
    const int wid = tid >> 5;
    const int warp_m = wid >> 2;        // 0..1  (64 rows each)
    const int warp_n = wid & 3;         // 0..3  (64 cols each)
    const int row0 = (blockIdx.x >> 2) * 128;   // row block
    const int n0   = (blockIdx.x & 3) * 256;    // u-pass
    const int b = row0 >> 12;

    float* vbuf = (float*)(smem + OFF_VH);
    float* hbuf = (float*)(smem + OFF_VH + 1024);
    float* red  = (float*)(smem + OFF_RED);

    const uint32_t a_loff = (uint32_t)((lane & 15) * ROWB + (lane >> 4) * 16);
    const uint32_t b_loff = (uint32_t)(((lane & 7) + ((lane >> 4) << 3)) * ROWB
                                       + ((lane >> 3) & 1) * 16);

    vbuf[tid] = V[n0 + tid];
    hbuf[tid] = g_hpb[b * U_ + n0 + tid];

    float acc[4][8][4];                // 128 fp32 accumulators
    #pragma unroll
    for (int mt = 0; mt < 4; mt++)
        #pragma unroll
        for (int nt = 0; nt < 8; nt++)
            #pragma unroll
            for (int c = 0; c < 4; c++) acc[mt][nt][c] = 0.f;

    // ---- stage loader (K chunk of 64 into stage s), 256 threads ----
    auto load_stage = [&](int s, int k0) {
        const uint32_t stg = sb + s * STAGE_SZ;
        #pragma unroll
        for (int it = 0; it < 4; it++) {       // A: 128 rows x 8 chunks
            const int task = tid + it * 256;
            const int r = task >> 3, c = task & 7;
            const __half* src = g_Xhi + (size_t)(row0 + r) * D_ + k0 + c * 8;
            CP_ASYNC16(stg + r * ROWB + c * 16, src);
        }
        #pragma unroll
        for (int it = 0; it < 8; it++) {       // B: 256 rows x 8 chunks
            const int task = tid + it * 256;
            const int r = task >> 3, c = task & 7;
            const __half* src = g_Whi + (size_t)(n0 + r) * D_ + k0 + c * 8;
            CP_ASYNC16(stg + OFF_B + r * ROWB + c * 16, src);
        }
    };

    load_stage(0, 0);   CP_COMMIT();
    load_stage(1, 64);  CP_COMMIT();

    #pragma unroll 1
    for (int kc = 0; kc < 16; kc++) {
        CP_WAIT1();
        __syncthreads();
        if (kc + 2 < 16) load_stage((kc + 2) % NSTAGE, (kc + 2) * 64);
        CP_COMMIT();

        const uint32_t stg = sb + (kc % NSTAGE) * STAGE_SZ;
        const uint32_t aBase = stg + warp_m * 64 * ROWB + a_loff;
        const uint32_t bBase = stg + OFF_B + warp_n * 64 * ROWB + b_loff;

        #pragma unroll
        for (int k16 = 0; k16 < 4; k16++) {
            const uint32_t ko = k16 * 32;      // 16 fp16 = 32 bytes
            uint32_t af[4][4], bf[4][4];
            #pragma unroll
            for (int i = 0; i < 4; i++)
                ldm_x4(bf[i], bBase + i * 16 * ROWB + ko);
            #pragma unroll
            for (int mt = 0; mt < 4; mt++)
                ldm_x4(af[mt], aBase + mt * 16 * ROWB + ko);
            #pragma unroll
            for (int mt = 0; mt < 4; mt++)
                #pragma unroll
                for (int nt = 0; nt < 8; nt++)
                    mma_fp16(acc[mt][nt], af[mt], &bf[nt >> 1][(nt & 1) * 2]);
        }
    }

    // ---- epilogue: fold tanh + V into per-row partials ----
    float rowsum8[8];
    #pragma unroll
    for (int j = 0; j < 8; j++) rowsum8[j] = 0.f;
    #pragma unroll
    for (int mt = 0; mt < 4; mt++)
        #pragma unroll
        for (int nt = 0; nt < 8; nt++)
            #pragma unroll
            for (int c = 0; c < 4; c++) {
                const int ul = warp_n * 64 + nt * 8 + (lane & 3) * 2 + (c & 1);
                const float s = acc[mt][nt][c] + hbuf[ul];
                rowsum8[mt * 2 + (c >> 1)] =
                    fmaf(vbuf[ul], fast_tanh(s), rowsum8[mt * 2 + (c >> 1)]);
            }

    // cross-thread reduction: quad-shfl, then 4 warp_n slices via smem
    #pragma unroll
    for (int j = 0; j < 8; j++) {
        float v = rowsum8[j];
        v += __shfl_xor_sync(0xffffffffu, v, 1);
        v += __shfl_xor_sync(0xffffffffu, v, 2);
        if ((lane & 3) == 0) {
            const int r = warp_m * 64 + (j >> 1) * 16 + (lane >> 2) + 8 * (j & 1);
            red[r * 4 + warp_n] = v;
        }
    }
    __syncthreads();
    if (tid < 128)
        atomicAdd(&g_score[row0 + tid],
                  red[tid * 4 + 0] + red[tid * 4 + 1]
                + red[tid * 4 + 2] + red[tid * 4 + 3]);
}

// ---------------------------------------------------------------------------
// Kernel E: softmax over T per batch, 1024 threads (latency-bound fix)
// ---------------------------------------------------------------------------
__global__ void softmax_kernel(float* __restrict__ wout) {
    const int b = blockIdx.x;
    const float* s = g_score + b * T_;
    float* w = wout + b * T_;
    __shared__ float red[1024];
    const int tid = threadIdx.x;

    float mx = -INFINITY;
    #pragma unroll
    for (int t = tid; t < T_; t += 1024) mx = fmaxf(mx, s[t]);
    red[tid] = mx; __syncthreads();
    for (int o = 512; o > 0; o >>= 1) {
        if (tid < o) red[tid] = fmaxf(red[tid], red[tid + o]);
        __syncthreads();
    }
    mx = red[0]; __syncthreads();

    float sum = 0.f;
    #pragma unroll
    for (int t = tid; t < T_; t += 1024) {
        const float e = expf(s[t] - mx);
        w[t] = e;
        sum += e;
    }
    red[tid] = sum; __syncthreads();
    for (int o = 512; o > 0; o >>= 1) {
        if (tid < o) red[tid] += red[tid + o];
        __syncthreads();
    }
    const float inv = 1.f / red[0];
    #pragma unroll
    for (int t = tid; t < T_; t += 1024) w[t] *= inv;
}

// ---------------------------------------------------------------------------
// Kernel F: context[b,d] = sum_t w[b,t] * enc_fp16[b,t,d]
// half2 loads -> full 128B/warp coalescing (was 64B with scalar __half).
// ---------------------------------------------------------------------------
__global__ void context_kernel(const float* __restrict__ w,
                               float* __restrict__ ctx) {
    const int b  = blockIdx.y;
    const int t0 = blockIdx.x * 128;
    const int tid = threadIdx.x;
    float2 c0 = {0.f, 0.f}, c1 = {0.f, 0.f};
    for (int t = t0; t < t0 + 128; t++) {
        const float wt = w[b * T_ + t];
        const __half2* row = (const __half2*)(g_Xhi + ((size_t)b * T_ + t) * D_);
        const float2 fa = __half22float2(row[tid]);         // d = 2tid, 2tid+1
        const float2 fb = __half22float2(row[tid + 256]);   // d = 512+2tid, +1
        c0.x = fmaf(wt, fa.x, c0.x);
        c0.y = fmaf(wt, fa.y, c0.y);
        c1.x = fmaf(wt, fb.x, c1.x);
        c1.y = fmaf(wt, fb.y, c1.y);
    }
    atomicAdd(&ctx[b * D_ + 2 * tid + 0],   c0.x);
    atomicAdd(&ctx[b * D_ + 2 * tid + 1],   c0.y);
    atomicAdd(&ctx[b * D_ + 512 + 2 * tid + 0], c1.x);
    atomicAdd(&ctx[b * D_ + 512 + 2 * tid + 1], c1.y);
}

// ---------------------------------------------------------------------------
extern "C" void kernel_launch(void* const* d_in, const int* in_sizes, int n_in,
                              void* d_out, int out_size) {
    const float* h   = (const float*)d_in[0];  // [B, D]
    const float* enc = (const float*)d_in[1];  // [B, T, D]
    const float* W1  = (const float*)d_in[2];  // [D, U]
    const float* b1  = (const float*)d_in[3];  // [U]
    const float* W2  = (const float*)d_in[4];  // [D, U]
    const float* b2  = (const float*)d_in[5];  // [U]
    const float* V   = (const float*)d_in[6];  // [U, 1]
    // d_in[7] = bv: softmax-invariant constant, unused.

    float* out = (float*)d_out;
    float* ctx = out;             // [B, D]
    float* wts = out + B_ * D_;   // [B, T, 1]

    cudaFuncSetAttribute(score_kernel,
                         cudaFuncAttributeMaxDynamicSharedMemorySize, SK_SMEM);

    void* scorePtr = nullptr;
    cudaGetSymbolAddress(&scorePtr, g_score);

    cudaMemsetAsync(ctx, 0, (size_t)B_ * D_ * sizeof(float));
    cudaMemsetAsync(scorePtr, 0, (size_t)M_ * sizeof(float));

    convert_x_kernel<<<(M_ * D_) / (256 * 8), 256>>>(enc);
    convert_w_kernel<<<dim3(32, 32), dim3(32, 8)>>>(W2);
    hproj_kernel<<<dim3(U_ / 256, B_), 256>>>(h, W1, b1, b2);
    score_kernel<<<4 * (M_ / 128), 256, SK_SMEM>>>(V);
    softmax_kernel<<<B_, 1024>>>(wts);
    context_kernel<<<dim3(T_ / 128, B_), 256>>>(wts, ctx);
}

// round 15
// speedup vs baseline: 1.3052x; 1.0010x over previous
#include <cuda_runtime.h>
#include <cuda_fp16.h>
#include <math.h>
#include <stdint.h>

// Problem constants
#define B_  16
#define T_  4096
#define D_  1024
#define U_  1024
#define M_  (B_ * T_)   // 65536 rows

// ---------------------------------------------------------------------------
// Device-global scratch (no allocations allowed)
// ---------------------------------------------------------------------------
__device__ __half g_Xhi[(size_t)M_ * D_];   // 128 MiB  (fp16 of enc)
__device__ __half g_Whi[(size_t)U_ * D_];   // W2^T [u][d] fp16
__device__ float g_hpb[B_ * U_];
__device__ float g_score[M_];

// ---------------------------------------------------------------------------
// Helpers
// ---------------------------------------------------------------------------
__device__ __forceinline__ uint32_t smem_u32(const void* p) {
    uint32_t a;
    asm("{ .reg .u64 t; cvta.to.shared.u64 t, %1; cvt.u32.u64 %0, t; }" : "=r"(a) : "l"(p));
    return a;
}
#define CP_ASYNC16(dst, src) \
    asm volatile("cp.async.cg.shared.global [%0], [%1], 16;" :: "r"(dst), "l"(src))
#define CP_COMMIT() asm volatile("cp.async.commit_group;" ::: "memory")
#define CP_WAIT1()  asm volatile("cp.async.wait_group 1;" ::: "memory")

__device__ __forceinline__ void ldm_x4(uint32_t* r, uint32_t addr) {
    asm volatile("ldmatrix.sync.aligned.m8n8.x4.shared.b16 {%0,%1,%2,%3}, [%4];"
                 : "=r"(r[0]), "=r"(r[1]), "=r"(r[2]), "=r"(r[3]) : "r"(addr));
}
__device__ __forceinline__ void mma_fp16(float* c, const uint32_t* a, const uint32_t* b) {
    asm volatile(
        "mma.sync.aligned.m16n8k16.row.col.f32.f16.f16.f32 "
        "{%0,%1,%2,%3}, {%4,%5,%6,%7}, {%8,%9}, {%0,%1,%2,%3};"
        : "+f"(c[0]), "+f"(c[1]), "+f"(c[2]), "+f"(c[3])
        : "r"(a[0]), "r"(a[1]), "r"(a[2]), "r"(a[3]), "r"(b[0]), "r"(b[1]));
}

// FMA-only fast tanh (abs err ~1e-6); avoids MUFU entirely.
__device__ __forceinline__ float fast_tanh(float x) {
    float ax = fabsf(x);
    float t = fminf(ax * 2.885390082f, 30.0f);     // 2|x|*log2(e)
    float nt = -t;
    float fi = floorf(nt);
    float f = nt - fi;                              // [0,1)
    float p =              1.5253232e-5f;
    p = fmaf(p, f, 1.5403530e-4f);
    p = fmaf(p, f, 1.3333558e-3f);
    p = fmaf(p, f, 9.6181291e-3f);
    p = fmaf(p, f, 5.5504109e-2f);
    p = fmaf(p, f, 2.4022651e-1f);
    p = fmaf(p, f, 6.9314718e-1f);
    p = fmaf(p, f, 1.0f);
    int ei = (int)fi;                               // [-30, 0]
    float e = __int_as_float((ei + 127) << 23) * p; // 2^nt = e^{-2|x|}
    float d = 1.0f + e;
    float r = __int_as_float(0x7EF311C3u - __float_as_int(d));
    r = r * (2.0f - d * r);
    r = r * (2.0f - d * r);
    r = r * (2.0f - d * r);
    float y = (1.0f - e) * r;
    return copysignf(y, x);
}

// ---------------------------------------------------------------------------
// Kernel A: enc fp32 -> fp16.  32 elems/thread (8 float4 loads in flight).
// ---------------------------------------------------------------------------
__global__ void convert_x_kernel(const float* __restrict__ X) {
    const size_t base = ((size_t)blockIdx.x * 256 + threadIdx.x) * 32;
    float4 f[8];
    #pragma unroll
    for (int j = 0; j < 8; j++)
        f[j] = *(const float4*)(X + base + j * 4);
    #pragma unroll
    for (int j = 0; j < 8; j += 2) {
        __half2 h0 = __floats2half2_rn(f[j].x,   f[j].y);
        __half2 h1 = __floats2half2_rn(f[j].z,   f[j].w);
        __half2 h2 = __floats2half2_rn(f[j+1].x, f[j+1].y);
        __half2 h3 = __floats2half2_rn(f[j+1].z, f[j+1].w);
        uint4 st;
        st.x = *(uint32_t*)&h0; st.y = *(uint32_t*)&h1;
        st.z = *(uint32_t*)&h2; st.w = *(uint32_t*)&h3;
        *(uint4*)(g_Xhi + base + j * 4) = st;
    }
}

// ---------------------------------------------------------------------------
// Kernel B: transpose W2 [d][u] -> [u][d] fp16
// ---------------------------------------------------------------------------
__global__ void convert_w_kernel(const float* __restrict__ W2) {
    __shared__ float tile[32][33];
    const int u0 = blockIdx.x * 32, d0 = blockIdx.y * 32;
    const int tx = threadIdx.x, ty = threadIdx.y;           // (32, 8)
    #pragma unroll
    for (int j = 0; j < 32; j += 8)
        tile[ty + j][tx] = W2[(size_t)(d0 + ty + j) * U_ + u0 + tx];
    __syncthreads();
    #pragma unroll
    for (int j = 0; j < 32; j += 8)
        g_Whi[(size_t)(u0 + ty + j) * D_ + d0 + tx] =
            __float2half_rn(tile[tx][ty + j]);
}

// ---------------------------------------------------------------------------
// Kernel C: hpb[b,u] = h@W1 + b1 + b2.  4 independent accumulators (chain/4).
// ---------------------------------------------------------------------------
__global__ void hproj_kernel(const float* __restrict__ h,
                             const float* __restrict__ W1,
                             const float* __restrict__ b1,
                             const float* __restrict__ b2) {
    __shared__ float hs[D_];
    const int b = blockIdx.y;
    const int u = blockIdx.x * 256 + threadIdx.x;
    for (int i = threadIdx.x; i < D_; i += 256) hs[i] = h[b * D_ + i];
    __syncthreads();
    float a0 = 0.f, a1 = 0.f, a2 = 0.f, a3 = 0.f;
    #pragma unroll 4
    for (int d = 0; d < D_; d += 4) {
        a0 = fmaf(hs[d + 0], W1[(size_t)(d + 0) * U_ + u], a0);
        a1 = fmaf(hs[d + 1], W1[(size_t)(d + 1) * U_ + u], a1);
        a2 = fmaf(hs[d + 2], W1[(size_t)(d + 2) * U_ + u], a2);
        a3 = fmaf(hs[d + 3], W1[(size_t)(d + 3) * U_ + u], a3);
    }
    g_hpb[b * U_ + u] = (a0 + a1) + (a2 + a3) + b1[u] + b2[u];
}

// ---------------------------------------------------------------------------
// Kernel D: score GEMM via mma.sync fp16 (single product), fused tanh/V
// epilogue. Grid = 2048 (row-block x u-pass), atomicAdd partial row sums.
// K chunks of 64, 3-stage cp.async pipeline, 256 threads / 8 warps,
// 64x64 warp tiles. (R9 structure — at the HMMA issue-rate wall.)
// ---------------------------------------------------------------------------
#define ROWB     144                      // 128 B data + 16 B pad
#define A_TILE   (128 * ROWB)             // 18432
#define B_TILE   (256 * ROWB)             // 36864
#define STAGE_SZ (A_TILE + B_TILE)        // 55296
#define OFF_B    A_TILE
#define NSTAGE   3
#define OFF_VH   (NSTAGE * STAGE_SZ)      // 165888
#define OFF_RED  (OFF_VH + 2048)
#define SK_SMEM  (OFF_RED + 4096)         // 172032

__global__ void __launch_bounds__(256, 1)
score_kernel(const float* __restrict__ V) {
    extern __shared__ char smem[];
    const uint32_t sb = smem_u32(smem);
    const int tid = threadIdx.x;
    const int lane = tid & 31;
    const int wid = tid >> 5;
    const int warp_m = wid >> 2;        // 0..1  (64 rows each)
    const int warp_n = wid & 3;         // 0..3  (64 cols each)
    const int row0 = (blockIdx.x >> 2) * 128;   // row block
    const int n0   = (blockIdx.x & 3) * 256;    // u-pass
    const int b = row0 >> 12;

    float* vbuf = (float*)(smem + OFF_VH);
    float* hbuf = (float*)(smem + OFF_VH + 1024);
    float* red  = (float*)(smem + OFF_RED);

    const uint32_t a_loff = (uint32_t)((lane & 15) * ROWB + (lane >> 4) * 16);
    const uint32_t b_loff = (uint32_t)(((lane & 7) + ((lane >> 4) << 3)) * ROWB
                                       + ((lane >> 3) & 1) * 16);

    vbuf[tid] = V[n0 + tid];
    hbuf[tid] = g_hpb[b * U_ + n0 + tid];

    float acc[4][8][4];                // 128 fp32 accumulators
    #pragma unroll
    for (int mt = 0; mt < 4; mt++)
        #pragma unroll
        for (int nt = 0; nt < 8; nt++)
            #pragma unroll
            for (int c = 0; c < 4; c++) acc[mt][nt][c] = 0.f;

    // ---- stage loader (K chunk of 64 into stage s), 256 threads ----
    auto load_stage = [&](int s, int k0) {
        const uint32_t stg = sb + s * STAGE_SZ;
        #pragma unroll
        for (int it = 0; it < 4; it++) {       // A: 128 rows x 8 chunks
            const int task = tid + it * 256;
            const int r = task >> 3, c = task & 7;
            const __half* src = g_Xhi + (size_t)(row0 + r) * D_ + k0 + c * 8;
            CP_ASYNC16(stg + r * ROWB + c * 16, src);
        }
        #pragma unroll
        for (int it = 0; it < 8; it++) {       // B: 256 rows x 8 chunks
            const int task = tid + it * 256;
            const int r = task >> 3, c = task & 7;
            const __half* src = g_Whi + (size_t)(n0 + r) * D_ + k0 + c * 8;
            CP_ASYNC16(stg + OFF_B + r * ROWB + c * 16, src);
        }
    };

    load_stage(0, 0);   CP_COMMIT();
    load_stage(1, 64);  CP_COMMIT();

    #pragma unroll 1
    for (int kc = 0; kc < 16; kc++) {
        CP_WAIT1();
        __syncthreads();
        if (kc + 2 < 16) load_stage((kc + 2) % NSTAGE, (kc + 2) * 64);
        CP_COMMIT();

        const uint32_t stg = sb + (kc % NSTAGE) * STAGE_SZ;
        const uint32_t aBase = stg + warp_m * 64 * ROWB + a_loff;
        const uint32_t bBase = stg + OFF_B + warp_n * 64 * ROWB + b_loff;

        #pragma unroll
        for (int k16 = 0; k16 < 4; k16++) {
            const uint32_t ko = k16 * 32;      // 16 fp16 = 32 bytes
            uint32_t af[4][4], bf[4][4];
            #pragma unroll
            for (int i = 0; i < 4; i++)
                ldm_x4(bf[i], bBase + i * 16 * ROWB + ko);
            #pragma unroll
            for (int mt = 0; mt < 4; mt++)
                ldm_x4(af[mt], aBase + mt * 16 * ROWB + ko);
            #pragma unroll
            for (int mt = 0; mt < 4; mt++)
                #pragma unroll
                for (int nt = 0; nt < 8; nt++)
                    mma_fp16(acc[mt][nt], af[mt], &bf[nt >> 1][(nt & 1) * 2]);
        }
    }

    // ---- epilogue: fold tanh + V into per-row partials ----
    float rowsum8[8];
    #pragma unroll
    for (int j = 0; j < 8; j++) rowsum8[j] = 0.f;
    #pragma unroll
    for (int mt = 0; mt < 4; mt++)
        #pragma unroll
        for (int nt = 0; nt < 8; nt++)
            #pragma unroll
            for (int c = 0; c < 4; c++) {
                const int ul = warp_n * 64 + nt * 8 + (lane & 3) * 2 + (c & 1);
                const float s = acc[mt][nt][c] + hbuf[ul];
                rowsum8[mt * 2 + (c >> 1)] =
                    fmaf(vbuf[ul], fast_tanh(s), rowsum8[mt * 2 + (c >> 1)]);
            }

    // cross-thread reduction: quad-shfl, then 4 warp_n slices via smem
    #pragma unroll
    for (int j = 0; j < 8; j++) {
        float v = rowsum8[j];
        v += __shfl_xor_sync(0xffffffffu, v, 1);
        v += __shfl_xor_sync(0xffffffffu, v, 2);
        if ((lane & 3) == 0) {
            const int r = warp_m * 64 + (j >> 1) * 16 + (lane >> 2) + 8 * (j & 1);
            red[r * 4 + warp_n] = v;
        }
    }
    __syncthreads();
    if (tid < 128)
        atomicAdd(&g_score[row0 + tid],
                  red[tid * 4 + 0] + red[tid * 4 + 1]
                + red[tid * 4 + 2] + red[tid * 4 + 3]);
}

// ---------------------------------------------------------------------------
// Kernel E: softmax over T per batch, 1024 threads
// ---------------------------------------------------------------------------
__global__ void softmax_kernel(float* __restrict__ wout) {
    const int b = blockIdx.x;
    const float* s = g_score + b * T_;
    float* w = wout + b * T_;
    __shared__ float red[1024];
    const int tid = threadIdx.x;

    float mx = -INFINITY;
    #pragma unroll
    for (int t = tid; t < T_; t += 1024) mx = fmaxf(mx, s[t]);
    red[tid] = mx; __syncthreads();
    for (int o = 512; o > 0; o >>= 1) {
        if (tid < o) red[tid] = fmaxf(red[tid], red[tid + o]);
        __syncthreads();
    }
    mx = red[0]; __syncthreads();

    float sum = 0.f;
    #pragma unroll
    for (int t = tid; t < T_; t += 1024) {
        const float e = expf(s[t] - mx);
        w[t] = e;
        sum += e;
    }
    red[tid] = sum; __syncthreads();
    for (int o = 512; o > 0; o >>= 1) {
        if (tid < o) red[tid] += red[tid + o];
        __syncthreads();
    }
    const float inv = 1.f / red[0];
    #pragma unroll
    for (int t = tid; t < T_; t += 1024) w[t] *= inv;
}

// ---------------------------------------------------------------------------
// Kernel F: context[b,d] = sum_t w[b,t] * enc_fp16[b,t,d]  (half2 coalesced)
// ---------------------------------------------------------------------------
__global__ void context_kernel(const float* __restrict__ w,
                               float* __restrict__ ctx) {
    const int b  = blockIdx.y;
    const int t0 = blockIdx.x * 128;
    const int tid = threadIdx.x;
    float2 c0 = {0.f, 0.f}, c1 = {0.f, 0.f};
    for (int t = t0; t < t0 + 128; t++) {
        const float wt = w[b * T_ + t];
        const __half2* row = (const __half2*)(g_Xhi + ((size_t)b * T_ + t) * D_);
        const float2 fa = __half22float2(row[tid]);
        const float2 fb = __half22float2(row[tid + 256]);
        c0.x = fmaf(wt, fa.x, c0.x);
        c0.y = fmaf(wt, fa.y, c0.y);
        c1.x = fmaf(wt, fb.x, c1.x);
        c1.y = fmaf(wt, fb.y, c1.y);
    }
    atomicAdd(&ctx[b * D_ + 2 * tid + 0],   c0.x);
    atomicAdd(&ctx[b * D_ + 2 * tid + 1],   c0.y);
    atomicAdd(&ctx[b * D_ + 512 + 2 * tid + 0], c1.x);
    atomicAdd(&ctx[b * D_ + 512 + 2 * tid + 1], c1.y);
}

// ---------------------------------------------------------------------------
extern "C" void kernel_launch(void* const* d_in, const int* in_sizes, int n_in,
                              void* d_out, int out_size) {
    const float* h   = (const float*)d_in[0];  // [B, D]
    const float* enc = (const float*)d_in[1];  // [B, T, D]
    const float* W1  = (const float*)d_in[2];  // [D, U]
    const float* b1  = (const float*)d_in[3];  // [U]
    const float* W2  = (const float*)d_in[4];  // [D, U]
    const float* b2  = (const float*)d_in[5];  // [U]
    const float* V   = (const float*)d_in[6];  // [U, 1]
    // d_in[7] = bv: softmax-invariant constant, unused.

    float* out = (float*)d_out;
    float* ctx = out;             // [B, D]
    float* wts = out + B_ * D_;   // [B, T, 1]

    cudaFuncSetAttribute(score_kernel,
                         cudaFuncAttributeMaxDynamicSharedMemorySize, SK_SMEM);

    void* scorePtr = nullptr;
    cudaGetSymbolAddress(&scorePtr, g_score);

    cudaMemsetAsync(ctx, 0, (size_t)B_ * D_ * sizeof(float));
    cudaMemsetAsync(scorePtr, 0, (size_t)M_ * sizeof(float));

    convert_x_kernel<<<(M_ * D_) / (256 * 32), 256>>>(enc);
    convert_w_kernel<<<dim3(32, 32), dim3(32, 8)>>>(W2);
    hproj_kernel<<<dim3(U_ / 256, B_), 256>>>(h, W1, b1, b2);
    score_kernel<<<4 * (M_ / 128), 256, SK_SMEM>>>(V);
    softmax_kernel<<<B_, 1024>>>(wts);
    context_kernel<<<dim3(T_ / 128, B_), 256>>>(wts, ctx);
}

// round 16
// speedup vs baseline: 1.3257x; 1.0157x over previous
#include <cuda_runtime.h>
#include <cuda_fp16.h>
#include <math.h>
#include <stdint.h>

// Problem constants
#define B_  16
#define T_  4096
#define D_  1024
#define U_  1024
#define M_  (B_ * T_)   // 65536 rows

// ---------------------------------------------------------------------------
// Device-global scratch (no allocations allowed)
// ---------------------------------------------------------------------------
__device__ __half g_Xhi[(size_t)M_ * D_];   // fp16 of enc (published by n0==0 CTAs)
__device__ __half g_Whi[(size_t)U_ * D_];   // W2^T [u][d] fp16
__device__ float g_hpb[B_ * U_];
__device__ float g_score[M_];

// ---------------------------------------------------------------------------
// Helpers
// ---------------------------------------------------------------------------
__device__ __forceinline__ uint32_t smem_u32(const void* p) {
    uint32_t a;
    asm("{ .reg .u64 t; cvta.to.shared.u64 t, %1; cvt.u32.u64 %0, t; }" : "=r"(a) : "l"(p));
    return a;
}
#define CP_ASYNC16(dst, src) \
    asm volatile("cp.async.cg.shared.global [%0], [%1], 16;" :: "r"(dst), "l"(src))
#define CP_COMMIT() asm volatile("cp.async.commit_group;" ::: "memory")
#define CP_WAIT1()  asm volatile("cp.async.wait_group 1;" ::: "memory")

__device__ __forceinline__ void ldm_x4(uint32_t* r, uint32_t addr) {
    asm volatile("ldmatrix.sync.aligned.m8n8.x4.shared.b16 {%0,%1,%2,%3}, [%4];"
                 : "=r"(r[0]), "=r"(r[1]), "=r"(r[2]), "=r"(r[3]) : "r"(addr));
}
__device__ __forceinline__ void mma_fp16(float* c, const uint32_t* a, const uint32_t* b) {
    asm volatile(
        "mma.sync.aligned.m16n8k16.row.col.f32.f16.f16.f32 "
        "{%0,%1,%2,%3}, {%4,%5,%6,%7}, {%8,%9}, {%0,%1,%2,%3};"
        : "+f"(c[0]), "+f"(c[1]), "+f"(c[2]), "+f"(c[3])
        : "r"(a[0]), "r"(a[1]), "r"(a[2]), "r"(a[3]), "r"(b[0]), "r"(b[1]));
}

// FMA-only fast tanh (abs err ~1e-6); avoids MUFU entirely.
__device__ __forceinline__ float fast_tanh(float x) {
    float ax = fabsf(x);
    float t = fminf(ax * 2.885390082f, 30.0f);     // 2|x|*log2(e)
    float nt = -t;
    float fi = floorf(nt);
    float f = nt - fi;                              // [0,1)
    float p =              1.5253232e-5f;
    p = fmaf(p, f, 1.5403530e-4f);
    p = fmaf(p, f, 1.3333558e-3f);
    p = fmaf(p, f, 9.6181291e-3f);
    p = fmaf(p, f, 5.5504109e-2f);
    p = fmaf(p, f, 2.4022651e-1f);
    p = fmaf(p, f, 6.9314718e-1f);
    p = fmaf(p, f, 1.0f);
    int ei = (int)fi;                               // [-30, 0]
    float e = __int_as_float((ei + 127) << 23) * p; // 2^nt = e^{-2|x|}
    float d = 1.0f + e;
    float r = __int_as_float(0x7EF311C3u - __float_as_int(d));
    r = r * (2.0f - d * r);
    r = r * (2.0f - d * r);
    r = r * (2.0f - d * r);
    float y = (1.0f - e) * r;
    return copysignf(y, x);
}

// ---------------------------------------------------------------------------
// Kernel B: transpose W2 [d][u] -> [u][d] fp16
// ---------------------------------------------------------------------------
__global__ void convert_w_kernel(const float* __restrict__ W2) {
    __shared__ float tile[32][33];
    const int u0 = blockIdx.x * 32, d0 = blockIdx.y * 32;
    const int tx = threadIdx.x, ty = threadIdx.y;           // (32, 8)
    #pragma unroll
    for (int j = 0; j < 32; j += 8)
        tile[ty + j][tx] = W2[(size_t)(d0 + ty + j) * U_ + u0 + tx];
    __syncthreads();
    #pragma unroll
    for (int j = 0; j < 32; j += 8)
        g_Whi[(size_t)(u0 + ty + j) * D_ + d0 + tx] =
            __float2half_rn(tile[tx][ty + j]);
}

// ---------------------------------------------------------------------------
// Kernel C: hpb[b,u] = h@W1 + b1 + b2  (4 independent accumulators)
// ---------------------------------------------------------------------------
__global__ void hproj_kernel(const float* __restrict__ h,
                             const float* __restrict__ W1,
                             const float* __restrict__ b1,
                             const float* __restrict__ b2) {
    __shared__ float hs[D_];
    const int b = blockIdx.y;
    const int u = blockIdx.x * 256 + threadIdx.x;
    for (int i = threadIdx.x; i < D_; i += 256) hs[i] = h[b * D_ + i];
    __syncthreads();
    float a0 = 0.f, a1 = 0.f, a2 = 0.f, a3 = 0.f;
    #pragma unroll 4
    for (int d = 0; d < D_; d += 4) {
        a0 = fmaf(hs[d + 0], W1[(size_t)(d + 0) * U_ + u], a0);
        a1 = fmaf(hs[d + 1], W1[(size_t)(d + 1) * U_ + u], a1);
        a2 = fmaf(hs[d + 2], W1[(size_t)(d + 2) * U_ + u], a2);
        a3 = fmaf(hs[d + 3], W1[(size_t)(d + 3) * U_ + u], a3);
    }
    g_hpb[b * U_ + u] = (a0 + a1) + (a2 + a3) + b1[u] + b2[u];
}

// ---------------------------------------------------------------------------
// Kernel D: score GEMM (mma.sync fp16, single product) with A-conversion
// fused via LDG->reg->STS (bypasses the crossbar on the inbound side, so
// smem traffic ~= R9's). LDG for chunk kc+2 issued one iteration early.
// 512 threads / 16 warps, 64x32 warp tiles (acc=64 regs; staging fits).
// Grid = 2048 (row-block x u-pass); pass-adjacent CTAs share X rows in L2.
// n0==0 CTAs publish fp16 X to g_Xhi for context_kernel.
// ---------------------------------------------------------------------------
#define ROWB      144                     // fp16 row: 128 B data + 16 B pad
#define A16_TILE  (128 * ROWB)            // 18432 (x2 buffers)
#define B_TILE    (256 * ROWB)            // 36864 (x3 buffers)
#define OFF_B     (2 * A16_TILE)          // 36864
#define OFF_VH    (OFF_B + 3 * B_TILE)    // 147456
#define OFF_RED   (OFF_VH + 2048)         // 149504
#define SK_SMEM   (OFF_RED + 4096)        // 153600

__global__ void __launch_bounds__(512, 1)
score_kernel(const float* __restrict__ X, const float* __restrict__ V) {
    extern __shared__ char smem[];
    const uint32_t sb = smem_u32(smem);
    const int tid = threadIdx.x;
    const int lane = tid & 31;
    const int wid = tid >> 5;
    const int warp_m = wid >> 3;        // 0..1  (64 rows each)
    const int warp_n = wid & 7;         // 0..7  (32 cols each)
    const int row0 = (blockIdx.x >> 2) * 128;   // row block
    const int n0   = (blockIdx.x & 3) * 256;    // u-pass
    const int b = row0 >> 12;

    float* vbuf = (float*)(smem + OFF_VH);
    float* hbuf = (float*)(smem + OFF_VH + 1024);
    float* red  = (float*)(smem + OFF_RED);

    const uint32_t a_loff = (uint32_t)((lane & 15) * ROWB + (lane >> 4) * 16);
    const uint32_t b_loff = (uint32_t)(((lane & 7) + ((lane >> 4) << 3)) * ROWB
                                       + ((lane >> 3) & 1) * 16);

    if (tid < 256) {
        vbuf[tid] = V[n0 + tid];
        hbuf[tid] = g_hpb[b * U_ + n0 + tid];
    }

    float acc[4][4][4];                // 64 fp32 accumulators
    #pragma unroll
    for (int mt = 0; mt < 4; mt++)
        #pragma unroll
        for (int nt = 0; nt < 4; nt++)
            #pragma unroll
            for (int c = 0; c < 4; c++) acc[mt][nt][c] = 0.f;

    // A-conversion ownership: thread -> row (tid>>2), 16-float quarter (tid&3)
    const int cr = tid >> 2;
    const int cq = tid & 3;
    float4 f[4];                       // 16 staged fp32 (one chunk's worth)

    // ---- B loader: chunk j -> B[j%3] (fp16 via cp.async) ----
    auto loadB = [&](int j) {
        const int k0 = j * 64;
        const uint32_t bst = sb + OFF_B + (j % 3) * B_TILE;
        #pragma unroll
        for (int it = 0; it < 4; it++) {       // 2048 tasks / 512 threads
            const int task = tid + it * 512;
            const int r = task >> 3, c = task & 7;
            CP_ASYNC16(bst + r * ROWB + c * 16,
                       g_Whi + (size_t)(n0 + r) * D_ + k0 + c * 8);
        }
    };
    // ---- A stage: LDG own 16 fp32 of chunk j into registers ----
    auto ldgA = [&](int j) {
        const float* src = X + (size_t)(row0 + cr) * D_ + j * 64 + cq * 16;
        #pragma unroll
        for (int i = 0; i < 4; i++) f[i] = *(const float4*)(src + i * 4);
    };
    // ---- convert staged regs -> A16[j&1]; publish g_Xhi if pass 0 ----
    auto convertA = [&](int j) {
        __half2 h0 = __floats2half2_rn(f[0].x, f[0].y);
        __half2 h1 = __floats2half2_rn(f[0].z, f[0].w);
        __half2 h2 = __floats2half2_rn(f[1].x, f[1].y);
        __half2 h3 = __floats2half2_rn(f[1].z, f[1].w);
        __half2 h4 = __floats2half2_rn(f[2].x, f[2].y);
        __half2 h5 = __floats2half2_rn(f[2].z, f[2].w);
        __half2 h6 = __floats2half2_rn(f[3].x, f[3].y);
        __half2 h7 = __floats2half2_rn(f[3].z, f[3].w);
        uint4 s0, s1;
        s0.x = *(uint32_t*)&h0; s0.y = *(uint32_t*)&h1;
        s0.z = *(uint32_t*)&h2; s0.w = *(uint32_t*)&h3;
        s1.x = *(uint32_t*)&h4; s1.y = *(uint32_t*)&h5;
        s1.z = *(uint32_t*)&h6; s1.w = *(uint32_t*)&h7;
        char* dst = smem + (j & 1) * A16_TILE + cr * ROWB + cq * 32;
        *(uint4*)(dst + 0)  = s0;
        *(uint4*)(dst + 16) = s1;
        if (n0 == 0) {
            __half* g = g_Xhi + (size_t)(row0 + cr) * D_ + j * 64 + cq * 16;
            *(uint4*)(g + 0) = s0;
            *(uint4*)(g + 8) = s1;
        }
    };

    // ---- prologue ----
    loadB(0); CP_COMMIT();
    loadB(1); CP_COMMIT();
    ldgA(0);
    convertA(0);
    ldgA(1);
    CP_WAIT1();                 // B0 landed (own copies)
    __syncthreads();            // publish A16[0] + B0 to all warps

    #pragma unroll 1
    for (int kc = 0; kc < 16; kc++) {
        // MMA for chunk kc
        const uint32_t aBase = sb + (kc & 1) * A16_TILE
                             + warp_m * 64 * ROWB + a_loff;
        const uint32_t bBase = sb + OFF_B + (kc % 3) * B_TILE
                             + warp_n * 32 * ROWB + b_loff;
        #pragma unroll
        for (int k16 = 0; k16 < 4; k16++) {
            const uint32_t ko = k16 * 32;
            uint32_t af[4][4], bf[2][4];
            #pragma unroll
            for (int i = 0; i < 2; i++)
                ldm_x4(bf[i], bBase + i * 16 * ROWB + ko);
            #pragma unroll
            for (int mt = 0; mt < 4; mt++)
                ldm_x4(af[mt], aBase + mt * 16 * ROWB + ko);
            #pragma unroll
            for (int mt = 0; mt < 4; mt++)
                #pragma unroll
                for (int nt = 0; nt < 4; nt++)
                    mma_fp16(acc[mt][nt], af[mt], &bf[nt >> 1][(nt & 1) * 2]);
        }

        // convert chunk kc+1 (regs staged last iter) -> A16[(kc+1)&1]
        if (kc + 1 < 16) convertA(kc + 1);
        // stage chunk kc+2: LDG (regs) + cp.async B
        if (kc + 2 < 16) { ldgA(kc + 2); loadB(kc + 2); }
        CP_COMMIT();
        CP_WAIT1();             // B(kc+1) landed
        __syncthreads();        // publish A16[(kc+1)&1] + B(kc+1)
    }

    // ---- epilogue: fold tanh + V into per-row partials ----
    float rowsum8[8];
    #pragma unroll
    for (int j = 0; j < 8; j++) rowsum8[j] = 0.f;
    #pragma unroll
    for (int mt = 0; mt < 4; mt++)
        #pragma unroll
        for (int nt = 0; nt < 4; nt++)
            #pragma unroll
            for (int c = 0; c < 4; c++) {
                const int ul = warp_n * 32 + nt * 8 + (lane & 3) * 2 + (c & 1);
                const float s = acc[mt][nt][c] + hbuf[ul];
                rowsum8[mt * 2 + (c >> 1)] =
                    fmaf(vbuf[ul], fast_tanh(s), rowsum8[mt * 2 + (c >> 1)]);
            }

    // cross-thread reduction: quad-shfl, then 8 warp_n slices via smem
    #pragma unroll
    for (int j = 0; j < 8; j++) {
        float v = rowsum8[j];
        v += __shfl_xor_sync(0xffffffffu, v, 1);
        v += __shfl_xor_sync(0xffffffffu, v, 2);
        if ((lane & 3) == 0) {
            const int r = warp_m * 64 + (j >> 1) * 16 + (lane >> 2) + 8 * (j & 1);
            red[r * 8 + warp_n] = v;
        }
    }
    __syncthreads();
    if (tid < 128) {
        float s = 0.f;
        #pragma unroll
        for (int j = 0; j < 8; j++) s += red[tid * 8 + j];
        atomicAdd(&g_score[row0 + tid], s);
    }
}

// ---------------------------------------------------------------------------
// Kernel E: softmax over T per batch, 1024 threads
// ---------------------------------------------------------------------------
__global__ void softmax_kernel(float* __restrict__ wout) {
    const int b = blockIdx.x;
    const float* s = g_score + b * T_;
    float* w = wout + b * T_;
    __shared__ float red[1024];
    const int tid = threadIdx.x;

    float mx = -INFINITY;
    #pragma unroll
    for (int t = tid; t < T_; t += 1024) mx = fmaxf(mx, s[t]);
    red[tid] = mx; __syncthreads();
    for (int o = 512; o > 0; o >>= 1) {
        if (tid < o) red[tid] = fmaxf(red[tid], red[tid + o]);
        __syncthreads();
    }
    mx = red[0]; __syncthreads();

    float sum = 0.f;
    #pragma unroll
    for (int t = tid; t < T_; t += 1024) {
        const float e = expf(s[t] - mx);
        w[t] = e;
        sum += e;
    }
    red[tid] = sum; __syncthreads();
    for (int o = 512; o > 0; o >>= 1) {
        if (tid < o) red[tid] += red[tid + o];
        __syncthreads();
    }
    const float inv = 1.f / red[0];
    #pragma unroll
    for (int t = tid; t < T_; t += 1024) w[t] *= inv;
}

// ---------------------------------------------------------------------------
// Kernel F: context[b,d] = sum_t w[b,t] * enc_fp16[b,t,d]  (half2 coalesced)
// ---------------------------------------------------------------------------
__global__ void context_kernel(const float* __restrict__ w,
                               float* __restrict__ ctx) {
    const int b  = blockIdx.y;
    const int t0 = blockIdx.x * 128;
    const int tid = threadIdx.x;
    float2 c0 = {0.f, 0.f}, c1 = {0.f, 0.f};
    for (int t = t0; t < t0 + 128; t++) {
        const float wt = w[b * T_ + t];
        const __half2* row = (const __half2*)(g_Xhi + ((size_t)b * T_ + t) * D_);
        const float2 fa = __half22float2(row[tid]);
        const float2 fb = __half22float2(row[tid + 256]);
        c0.x = fmaf(wt, fa.x, c0.x);
        c0.y = fmaf(wt, fa.y, c0.y);
        c1.x = fmaf(wt, fb.x, c1.x);
        c1.y = fmaf(wt, fb.y, c1.y);
    }
    atomicAdd(&ctx[b * D_ + 2 * tid + 0],   c0.x);
    atomicAdd(&ctx[b * D_ + 2 * tid + 1],   c0.y);
    atomicAdd(&ctx[b * D_ + 512 + 2 * tid + 0], c1.x);
    atomicAdd(&ctx[b * D_ + 512 + 2 * tid + 1], c1.y);
}

// ---------------------------------------------------------------------------
extern "C" void kernel_launch(void* const* d_in, const int* in_sizes, int n_in,
                              void* d_out, int out_size) {
    const float* h   = (const float*)d_in[0];  // [B, D]
    const float* enc = (const float*)d_in[1];  // [B, T, D]
    const float* W1  = (const float*)d_in[2];  // [D, U]
    const float* b1  = (const float*)d_in[3];  // [U]
    const float* W2  = (const float*)d_in[4];  // [D, U]
    const float* b2  = (const float*)d_in[5];  // [U]
    const float* V   = (const float*)d_in[6];  // [U, 1]
    // d_in[7] = bv: softmax-invariant constant, unused.

    float* out = (float*)d_out;
    float* ctx = out;             // [B, D]
    float* wts = out + B_ * D_;   // [B, T, 1]

    cudaFuncSetAttribute(score_kernel,
                         cudaFuncAttributeMaxDynamicSharedMemorySize, SK_SMEM);

    void* scorePtr = nullptr;
    cudaGetSymbolAddress(&scorePtr, g_score);

    cudaMemsetAsync(ctx, 0, (size_t)B_ * D_ * sizeof(float));
    cudaMemsetAsync(scorePtr, 0, (size_t)M_ * sizeof(float));

    convert_w_kernel<<<dim3(32, 32), dim3(32, 8)>>>(W2);
    hproj_kernel<<<dim3(U_ / 256, B_), 256>>>(h, W1, b1, b2);
    score_kernel<<<4 * (M_ / 128), 512, SK_SMEM>>>(enc, V);
    softmax_kernel<<<B_, 1024>>>(wts);
    context_kernel<<<dim3(T_ / 128, B_), 256>>>(wts, ctx);
}

// round 17
// speedup vs baseline: 1.3354x; 1.0074x over previous
#include <cuda_runtime.h>
#include <cuda_fp16.h>
#include <math.h>
#include <stdint.h>

// Problem constants
#define B_  16
#define T_  4096
#define D_  1024
#define U_  1024
#define M_  (B_ * T_)   // 65536 rows

// ---------------------------------------------------------------------------
// Device-global scratch (no allocations allowed)
// ---------------------------------------------------------------------------
__device__ __half g_Xhi[(size_t)M_ * D_];   // fp16 of enc (published by score CTAs)
__device__ __half g_Whi[(size_t)U_ * D_];   // W2^T [u][d] fp16
__device__ float g_hpb[B_ * U_];
__device__ float g_score[M_];

// ---------------------------------------------------------------------------
// Helpers
// ---------------------------------------------------------------------------
__device__ __forceinline__ uint32_t smem_u32(const void* p) {
    uint32_t a;
    asm("{ .reg .u64 t; cvta.to.shared.u64 t, %1; cvt.u32.u64 %0, t; }" : "=r"(a) : "l"(p));
    return a;
}
#define CP_ASYNC16(dst, src) \
    asm volatile("cp.async.cg.shared.global [%0], [%1], 16;" :: "r"(dst), "l"(src))
#define CP_COMMIT() asm volatile("cp.async.commit_group;" ::: "memory")
#define CP_WAIT1()  asm volatile("cp.async.wait_group 1;" ::: "memory")

__device__ __forceinline__ void ldm_x4(uint32_t* r, uint32_t addr) {
    asm volatile("ldmatrix.sync.aligned.m8n8.x4.shared.b16 {%0,%1,%2,%3}, [%4];"
                 : "=r"(r[0]), "=r"(r[1]), "=r"(r[2]), "=r"(r[3]) : "r"(addr));
}
__device__ __forceinline__ void mma_fp16(float* c, const uint32_t* a, const uint32_t* b) {
    asm volatile(
        "mma.sync.aligned.m16n8k16.row.col.f32.f16.f16.f32 "
        "{%0,%1,%2,%3}, {%4,%5,%6,%7}, {%8,%9}, {%0,%1,%2,%3};"
        : "+f"(c[0]), "+f"(c[1]), "+f"(c[2]), "+f"(c[3])
        : "r"(a[0]), "r"(a[1]), "r"(a[2]), "r"(a[3]), "r"(b[0]), "r"(b[1]));
}

// FMA-only fast tanh (abs err ~1e-6); avoids MUFU entirely.
__device__ __forceinline__ float fast_tanh(float x) {
    float ax = fabsf(x);
    float t = fminf(ax * 2.885390082f, 30.0f);     // 2|x|*log2(e)
    float nt = -t;
    float fi = floorf(nt);
    float f = nt - fi;                              // [0,1)
    float p =              1.5253232e-5f;
    p = fmaf(p, f, 1.5403530e-4f);
    p = fmaf(p, f, 1.3333558e-3f);
    p = fmaf(p, f, 9.6181291e-3f);
    p = fmaf(p, f, 5.5504109e-2f);
    p = fmaf(p, f, 2.4022651e-1f);
    p = fmaf(p, f, 6.9314718e-1f);
    p = fmaf(p, f, 1.0f);
    int ei = (int)fi;                               // [-30, 0]
    float e = __int_as_float((ei + 127) << 23) * p; // 2^nt = e^{-2|x|}
    float d = 1.0f + e;
    float r = __int_as_float(0x7EF311C3u - __float_as_int(d));
    r = r * (2.0f - d * r);
    r = r * (2.0f - d * r);
    r = r * (2.0f - d * r);
    float y = (1.0f - e) * r;
    return copysignf(y, x);
}

// ---------------------------------------------------------------------------
// Kernel B: transpose W2 [d][u] -> [u][d] fp16
// ---------------------------------------------------------------------------
__global__ void convert_w_kernel(const float* __restrict__ W2) {
    __shared__ float tile[32][33];
    const int u0 = blockIdx.x * 32, d0 = blockIdx.y * 32;
    const int tx = threadIdx.x, ty = threadIdx.y;           // (32, 8)
    #pragma unroll
    for (int j = 0; j < 32; j += 8)
        tile[ty + j][tx] = W2[(size_t)(d0 + ty + j) * U_ + u0 + tx];
    __syncthreads();
    #pragma unroll
    for (int j = 0; j < 32; j += 8)
        g_Whi[(size_t)(u0 + ty + j) * D_ + d0 + tx] =
            __float2half_rn(tile[tx][ty + j]);
}

// ---------------------------------------------------------------------------
// Kernel C: hpb[b,u] = h@W1 + b1 + b2  (4 independent accumulators)
// ---------------------------------------------------------------------------
__global__ void hproj_kernel(const float* __restrict__ h,
                             const float* __restrict__ W1,
                             const float* __restrict__ b1,
                             const float* __restrict__ b2) {
    __shared__ float hs[D_];
    const int b = blockIdx.y;
    const int u = blockIdx.x * 256 + threadIdx.x;
    for (int i = threadIdx.x; i < D_; i += 256) hs[i] = h[b * D_ + i];
    __syncthreads();
    float a0 = 0.f, a1 = 0.f, a2 = 0.f, a3 = 0.f;
    #pragma unroll 4
    for (int d = 0; d < D_; d += 4) {
        a0 = fmaf(hs[d + 0], W1[(size_t)(d + 0) * U_ + u], a0);
        a1 = fmaf(hs[d + 1], W1[(size_t)(d + 1) * U_ + u], a1);
        a2 = fmaf(hs[d + 2], W1[(size_t)(d + 2) * U_ + u], a2);
        a3 = fmaf(hs[d + 3], W1[(size_t)(d + 3) * U_ + u], a3);
    }
    g_hpb[b * U_ + u] = (a0 + a1) + (a2 + a3) + b1[u] + b2[u];
}

// ---------------------------------------------------------------------------
// Kernel D: score GEMM (mma.sync fp16, single product) with A-conversion
// fused via LDG->reg->STS. Publishing of fp16 X to g_Xhi is BALANCED:
// pass p publishes chunks with (kc & 3) == p (union covers all chunks with
// bit-identical values; per-CTA STG work uniform -> no straggler wave).
// 512 threads / 16 warps, 64x32 warp tiles, 2048 CTAs (row-block x u-pass).
// ---------------------------------------------------------------------------
#define ROWB      144                     // fp16 row: 128 B data + 16 B pad
#define A16_TILE  (128 * ROWB)            // 18432 (x2 buffers)
#define B_TILE    (256 * ROWB)            // 36864 (x3 buffers)
#define OFF_B     (2 * A16_TILE)          // 36864
#define OFF_VH    (OFF_B + 3 * B_TILE)    // 147456
#define OFF_RED   (OFF_VH + 2048)         // 149504
#define SK_SMEM   (OFF_RED + 4096)        // 153600

__global__ void __launch_bounds__(512, 1)
score_kernel(const float* __restrict__ X, const float* __restrict__ V) {
    extern __shared__ char smem[];
    const uint32_t sb = smem_u32(smem);
    const int tid = threadIdx.x;
    const int lane = tid & 31;
    const int wid = tid >> 5;
    const int warp_m = wid >> 3;        // 0..1  (64 rows each)
    const int warp_n = wid & 7;         // 0..7  (32 cols each)
    const int row0 = (blockIdx.x >> 2) * 128;   // row block
    const int pass = blockIdx.x & 3;            // u-pass
    const int n0   = pass * 256;
    const int b = row0 >> 12;

    float* vbuf = (float*)(smem + OFF_VH);
    float* hbuf = (float*)(smem + OFF_VH + 1024);
    float* red  = (float*)(smem + OFF_RED);

    const uint32_t a_loff = (uint32_t)((lane & 15) * ROWB + (lane >> 4) * 16);
    const uint32_t b_loff = (uint32_t)(((lane & 7) + ((lane >> 4) << 3)) * ROWB
                                       + ((lane >> 3) & 1) * 16);

    if (tid < 256) {
        vbuf[tid] = V[n0 + tid];
        hbuf[tid] = g_hpb[b * U_ + n0 + tid];
    }

    float acc[4][4][4];                // 64 fp32 accumulators
    #pragma unroll
    for (int mt = 0; mt < 4; mt++)
        #pragma unroll
        for (int nt = 0; nt < 4; nt++)
            #pragma unroll
            for (int c = 0; c < 4; c++) acc[mt][nt][c] = 0.f;

    // A-conversion ownership: thread -> row (tid>>2), 16-float quarter (tid&3)
    const int cr = tid >> 2;
    const int cq = tid & 3;
    float4 f[4];                       // 16 staged fp32 (one chunk's worth)

    // ---- B loader: chunk j -> B[j%3] (fp16 via cp.async) ----
    auto loadB = [&](int j) {
        const int k0 = j * 64;
        const uint32_t bst = sb + OFF_B + (j % 3) * B_TILE;
        #pragma unroll
        for (int it = 0; it < 4; it++) {       // 2048 tasks / 512 threads
            const int task = tid + it * 512;
            const int r = task >> 3, c = task & 7;
            CP_ASYNC16(bst + r * ROWB + c * 16,
                       g_Whi + (size_t)(n0 + r) * D_ + k0 + c * 8);
        }
    };
    // ---- A stage: LDG own 16 fp32 of chunk j into registers ----
    auto ldgA = [&](int j) {
        const float* src = X + (size_t)(row0 + cr) * D_ + j * 64 + cq * 16;
        #pragma unroll
        for (int i = 0; i < 4; i++) f[i] = *(const float4*)(src + i * 4);
    };
    // ---- convert staged regs -> A16[j&1]; publish chunk if (j&3)==pass ----
    auto convertA = [&](int j) {
        __half2 h0 = __floats2half2_rn(f[0].x, f[0].y);
        __half2 h1 = __floats2half2_rn(f[0].z, f[0].w);
        __half2 h2 = __floats2half2_rn(f[1].x, f[1].y);
        __half2 h3 = __floats2half2_rn(f[1].z, f[1].w);
        __half2 h4 = __floats2half2_rn(f[2].x, f[2].y);
        __half2 h5 = __floats2half2_rn(f[2].z, f[2].w);
        __half2 h6 = __floats2half2_rn(f[3].x, f[3].y);
        __half2 h7 = __floats2half2_rn(f[3].z, f[3].w);
        uint4 s0, s1;
        s0.x = *(uint32_t*)&h0; s0.y = *(uint32_t*)&h1;
        s0.z = *(uint32_t*)&h2; s0.w = *(uint32_t*)&h3;
        s1.x = *(uint32_t*)&h4; s1.y = *(uint32_t*)&h5;
        s1.z = *(uint32_t*)&h6; s1.w = *(uint32_t*)&h7;
        char* dst = smem + (j & 1) * A16_TILE + cr * ROWB + cq * 32;
        *(uint4*)(dst + 0)  = s0;
        *(uint4*)(dst + 16) = s1;
        if ((j & 3) == pass) {   // balanced publishing (1/4 of chunks per CTA)
            __half* g = g_Xhi + (size_t)(row0 + cr) * D_ + j * 64 + cq * 16;
            *(uint4*)(g + 0) = s0;
            *(uint4*)(g + 8) = s1;
        }
    };

    // ---- prologue ----
    loadB(0); CP_COMMIT();
    loadB(1); CP_COMMIT();
    ldgA(0);
    convertA(0);
    ldgA(1);
    CP_WAIT1();                 // B0 landed (own copies)
    __syncthreads();            // publish A16[0] + B0 to all warps

    #pragma unroll 1
    for (int kc = 0; kc < 16; kc++) {
        // MMA for chunk kc
        const uint32_t aBase = sb + (kc & 1) * A16_TILE
                             + warp_m * 64 * ROWB + a_loff;
        const uint32_t bBase = sb + OFF_B + (kc % 3) * B_TILE
                             + warp_n * 32 * ROWB + b_loff;
        #pragma unroll
        for (int k16 = 0; k16 < 4; k16++) {
            const uint32_t ko = k16 * 32;
            uint32_t af[4][4], bf[2][4];
            #pragma unroll
            for (int i = 0; i < 2; i++)
                ldm_x4(bf[i], bBase + i * 16 * ROWB + ko);
            #pragma unroll
            for (int mt = 0; mt < 4; mt++)
                ldm_x4(af[mt], aBase + mt * 16 * ROWB + ko);
            #pragma unroll
            for (int mt = 0; mt < 4; mt++)
                #pragma unroll
                for (int nt = 0; nt < 4; nt++)
                    mma_fp16(acc[mt][nt], af[mt], &bf[nt >> 1][(nt & 1) * 2]);
        }

        // convert chunk kc+1 (regs staged last iter) -> A16[(kc+1)&1]
        if (kc + 1 < 16) convertA(kc + 1);
        // stage chunk kc+2: LDG (regs) + cp.async B
        if (kc + 2 < 16) { ldgA(kc + 2); loadB(kc + 2); }
        CP_COMMIT();
        CP_WAIT1();             // B(kc+1) landed
        __syncthreads();        // publish A16[(kc+1)&1] + B(kc+1)
    }

    // ---- epilogue: fold tanh + V into per-row partials ----
    float rowsum8[8];
    #pragma unroll
    for (int j = 0; j < 8; j++) rowsum8[j] = 0.f;
    #pragma unroll
    for (int mt = 0; mt < 4; mt++)
        #pragma unroll
        for (int nt = 0; nt < 4; nt++)
            #pragma unroll
            for (int c = 0; c < 4; c++) {
                const int ul = warp_n * 32 + nt * 8 + (lane & 3) * 2 + (c & 1);
                const float s = acc[mt][nt][c] + hbuf[ul];
                rowsum8[mt * 2 + (c >> 1)] =
                    fmaf(vbuf[ul], fast_tanh(s), rowsum8[mt * 2 + (c >> 1)]);
            }

    // cross-thread reduction: quad-shfl, then 8 warp_n slices via smem
    #pragma unroll
    for (int j = 0; j < 8; j++) {
        float v = rowsum8[j];
        v += __shfl_xor_sync(0xffffffffu, v, 1);
        v += __shfl_xor_sync(0xffffffffu, v, 2);
        if ((lane & 3) == 0) {
            const int r = warp_m * 64 + (j >> 1) * 16 + (lane >> 2) + 8 * (j & 1);
            red[r * 8 + warp_n] = v;
        }
    }
    __syncthreads();
    if (tid < 128) {
        float s = 0.f;
        #pragma unroll
        for (int j = 0; j < 8; j++) s += red[tid * 8 + j];
        atomicAdd(&g_score[row0 + tid], s);
    }
}

// ---------------------------------------------------------------------------
// Kernel E: softmax over T per batch, 1024 threads
// ---------------------------------------------------------------------------
__global__ void softmax_kernel(float* __restrict__ wout) {
    const int b = blockIdx.x;
    const float* s = g_score + b * T_;
    float* w = wout + b * T_;
    __shared__ float red[1024];
    const int tid = threadIdx.x;

    float mx = -INFINITY;
    #pragma unroll
    for (int t = tid; t < T_; t += 1024) mx = fmaxf(mx, s[t]);
    red[tid] = mx; __syncthreads();
    for (int o = 512; o > 0; o >>= 1) {
        if (tid < o) red[tid] = fmaxf(red[tid], red[tid + o]);
        __syncthreads();
    }
    mx = red[0]; __syncthreads();

    float sum = 0.f;
    #pragma unroll
    for (int t = tid; t < T_; t += 1024) {
        const float e = expf(s[t] - mx);
        w[t] = e;
        sum += e;
    }
    red[tid] = sum; __syncthreads();
    for (int o = 512; o > 0; o >>= 1) {
        if (tid < o) red[tid] += red[tid + o];
        __syncthreads();
    }
    const float inv = 1.f / red[0];
    #pragma unroll
    for (int t = tid; t < T_; t += 1024) w[t] *= inv;
}

// ---------------------------------------------------------------------------
// Kernel F: context[b,d] = sum_t w[b,t] * enc_fp16[b,t,d]  (half2 coalesced)
// ---------------------------------------------------------------------------
__global__ void context_kernel(const float* __restrict__ w,
                               float* __restrict__ ctx) {
    const int b  = blockIdx.y;
    const int t0 = blockIdx.x * 128;
    const int tid = threadIdx.x;
    float2 c0 = {0.f, 0.f}, c1 = {0.f, 0.f};
    for (int t = t0; t < t0 + 128; t++) {
        const float wt = w[b * T_ + t];
        const __half2* row = (const __half2*)(g_Xhi + ((size_t)b * T_ + t) * D_);
        const float2 fa = __half22float2(row[tid]);
        const float2 fb = __half22float2(row[tid + 256]);
        c0.x = fmaf(wt, fa.x, c0.x);
        c0.y = fmaf(wt, fa.y, c0.y);
        c1.x = fmaf(wt, fb.x, c1.x);
        c1.y = fmaf(wt, fb.y, c1.y);
    }
    atomicAdd(&ctx[b * D_ + 2 * tid + 0],   c0.x);
    atomicAdd(&ctx[b * D_ + 2 * tid + 1],   c0.y);
    atomicAdd(&ctx[b * D_ + 512 + 2 * tid + 0], c1.x);
    atomicAdd(&ctx[b * D_ + 512 + 2 * tid + 1], c1.y);
}

// ---------------------------------------------------------------------------
extern "C" void kernel_launch(void* const* d_in, const int* in_sizes, int n_in,
                              void* d_out, int out_size) {
    const float* h   = (const float*)d_in[0];  // [B, D]
    const float* enc = (const float*)d_in[1];  // [B, T, D]
    const float* W1  = (const float*)d_in[2];  // [D, U]
    const float* b1  = (const float*)d_in[3];  // [U]
    const float* W2  = (const float*)d_in[4];  // [D, U]
    const float* b2  = (const float*)d_in[5];  // [U]
    const float* V   = (const float*)d_in[6];  // [U, 1]
    // d_in[7] = bv: softmax-invariant constant, unused.

    float* out = (float*)d_out;
    float* ctx = out;             // [B, D]
    float* wts = out + B_ * D_;   // [B, T, 1]

    cudaFuncSetAttribute(score_kernel,
                         cudaFuncAttributeMaxDynamicSharedMemorySize, SK_SMEM);

    void* scorePtr = nullptr;
    cudaGetSymbolAddress(&scorePtr, g_score);

    cudaMemsetAsync(ctx, 0, (size_t)B_ * D_ * sizeof(float));
    cudaMemsetAsync(scorePtr, 0, (size_t)M_ * sizeof(float));

    convert_w_kernel<<<dim3(32, 32), dim3(32, 8)>>>(W2);
    hproj_kernel<<<dim3(U_ / 256, B_), 256>>>(h, W1, b1, b2);
    score_kernel<<<4 * (M_ / 128), 512, SK_SMEM>>>(enc, V);
    softmax_kernel<<<B_, 1024>>>(wts);
    context_kernel<<<dim3(T_ / 128, B_), 256>>>(wts, ctx);
}